// round 1
// baseline (speedup 1.0000x reference)
#include <cuda_runtime.h>
#include <cuda_bf16.h>
#include <math_constants.h>

// Problem constants (shapes are fixed for this problem instance).
#define N_MAX 30000
#define M_MAX 10000

// Scratch (no cudaMalloc allowed -> __device__ globals).
__device__ unsigned long long g_row_best[N_MAX];   // packed (d2_bits<<32)|argmin_j
__device__ unsigned int       g_col_best[M_MAX];   // packed d2_bits
#define NB_RED 120
__device__ float g_partials[NB_RED];

// ---------------------------------------------------------------------------
// Init: poison the min arrays to +inf-equivalent.
// ---------------------------------------------------------------------------
__global__ void init_kernel(int n, int m) {
    int i = blockIdx.x * blockDim.x + threadIdx.x;
    if (i < n) g_row_best[i] = 0xFFFFFFFFFFFFFFFFull;
    if (i < m) g_col_best[i] = 0xFFFFFFFFu;
}

// ---------------------------------------------------------------------------
// Direction o->s: each thread owns one P row; loops over a chunk of Ps staged
// in shared memory.  Tracks min d2 + argmin, merges via packed u64 atomicMin.
// grid.x: row blocks, grid.y: column splits.
// ---------------------------------------------------------------------------
#define TILE_A 1024

__global__ __launch_bounds__(256)
void kernelA(const float* __restrict__ P, const float* __restrict__ Ps,
             int n, int m, int colChunk) {
    __shared__ float4 tile[TILE_A];

    const int row = blockIdx.x * blockDim.x + threadIdx.x;
    const int c0 = blockIdx.y * colChunk;
    const int c1 = min(c0 + colChunk, m);

    float px = 0.f, py = 0.f, pz = 0.f;
    if (row < n) {
        px = P[row * 3 + 0];
        py = P[row * 3 + 1];
        pz = P[row * 3 + 2];
    }

    float best = CUDART_INF_F;
    int bidx = 0;

    for (int t = c0; t < c1; t += TILE_A) {
        const int cnt = min(TILE_A, c1 - t);
        // cooperative tile load (pad w to 0)
        for (int k = threadIdx.x; k < cnt; k += blockDim.x) {
            const float* q = Ps + (size_t)(t + k) * 3;
            tile[k] = make_float4(q[0], q[1], q[2], 0.0f);
        }
        __syncthreads();

        if (row < n) {
            #pragma unroll 8
            for (int k = 0; k < cnt; k++) {
                float4 q = tile[k];              // broadcast LDS.128
                float dx = px - q.x;
                float dy = py - q.y;
                float dz = pz - q.z;
                float d2 = fmaf(dx, dx, fmaf(dy, dy, dz * dz));
                if (d2 < best) { best = d2; bidx = t + k; }
            }
        }
        __syncthreads();
    }

    if (row < n) {
        unsigned long long pk =
            ((unsigned long long)__float_as_uint(best) << 32) |
            (unsigned int)bidx;
        atomicMin(&g_row_best[row], pk);
    }
}

// ---------------------------------------------------------------------------
// Direction s->o: each thread owns one Ps row; loops over a chunk of P staged
// in shared memory.  Only min d2 needed (no argmin).
// grid.x: Ps blocks, grid.y: row splits.
// ---------------------------------------------------------------------------
#define TILE_B 1024

__global__ __launch_bounds__(256)
void kernelB(const float* __restrict__ P, const float* __restrict__ Ps,
             int n, int m, int rowChunk) {
    __shared__ float4 tile[TILE_B];

    const int col = blockIdx.x * blockDim.x + threadIdx.x;
    const int r0 = blockIdx.y * rowChunk;
    const int r1 = min(r0 + rowChunk, n);

    float qx = 0.f, qy = 0.f, qz = 0.f;
    if (col < m) {
        qx = Ps[col * 3 + 0];
        qy = Ps[col * 3 + 1];
        qz = Ps[col * 3 + 2];
    }

    float best = CUDART_INF_F;

    for (int t = r0; t < r1; t += TILE_B) {
        const int cnt = min(TILE_B, r1 - t);
        for (int k = threadIdx.x; k < cnt; k += blockDim.x) {
            const float* p = P + (size_t)(t + k) * 3;
            tile[k] = make_float4(p[0], p[1], p[2], 0.0f);
        }
        __syncthreads();

        if (col < m) {
            #pragma unroll 8
            for (int k = 0; k < cnt; k++) {
                float4 p = tile[k];
                float dx = qx - p.x;
                float dy = qy - p.y;
                float dz = qz - p.z;
                float d2 = fmaf(dx, dx, fmaf(dy, dy, dz * dz));
                best = fminf(best, d2);
            }
        }
        __syncthreads();
    }

    if (col < m) {
        atomicMin(&g_col_best[col], __float_as_uint(best));
    }
}

// ---------------------------------------------------------------------------
// Reduction stage 1: per-block partial sums (fixed block assignment ->
// deterministic).
// ---------------------------------------------------------------------------
__global__ __launch_bounds__(256)
void reduce_kernel(const float* __restrict__ prob, int n, int m) {
    __shared__ float ssum[256];
    const int stride = gridDim.x * blockDim.x;
    const int tid0 = blockIdx.x * blockDim.x + threadIdx.x;

    float s = 0.0f;
    // o->s term: sqrt(d2) * prob[argmin]
    for (int i = tid0; i < n; i += stride) {
        unsigned long long pk = g_row_best[i];
        float d2 = __uint_as_float((unsigned int)(pk >> 32));
        int j = (int)(unsigned int)(pk & 0xFFFFFFFFu);
        s += sqrtf(d2) * prob[j];
    }
    // s->o term: sqrt(d2) * prob[j]
    for (int i = tid0; i < m; i += stride) {
        float d2 = __uint_as_float(g_col_best[i]);
        s += sqrtf(d2) * prob[i];
    }

    ssum[threadIdx.x] = s;
    __syncthreads();
    // deterministic tree reduction
    for (int off = 128; off > 0; off >>= 1) {
        if (threadIdx.x < off) ssum[threadIdx.x] += ssum[threadIdx.x + off];
        __syncthreads();
    }
    if (threadIdx.x == 0) g_partials[blockIdx.x] = ssum[0];
}

// ---------------------------------------------------------------------------
// Reduction stage 2: single thread sums the fixed partials sequentially
// (deterministic), writes the scalar loss.
// ---------------------------------------------------------------------------
__global__ void final_kernel(float* __restrict__ out, int nb) {
    if (threadIdx.x == 0 && blockIdx.x == 0) {
        float s = 0.0f;
        for (int i = 0; i < nb; i++) s += g_partials[i];
        out[0] = s;
    }
}

// ---------------------------------------------------------------------------
// Launch
// ---------------------------------------------------------------------------
extern "C" void kernel_launch(void* const* d_in, const int* in_sizes, int n_in,
                              void* d_out, int out_size) {
    const float* P    = (const float*)d_in[0];
    const float* Ps   = (const float*)d_in[1];
    const float* prob = (const float*)d_in[2];
    float* out = (float*)d_out;

    const int n = in_sizes[0] / 3;   // 30000
    const int m = in_sizes[1] / 3;   // 10000

    // init
    {
        int total = max(n, m);
        init_kernel<<<(total + 255) / 256, 256>>>(n, m);
    }

    // o->s: row blocks x column splits
    {
        const int GY = 5;
        const int colChunk = (m + GY - 1) / GY;
        dim3 grid((n + 255) / 256, GY);
        kernelA<<<grid, 256>>>(P, Ps, n, m, colChunk);
    }

    // s->o: Ps blocks x row splits
    {
        const int GY = 15;
        const int rowChunk = (n + GY - 1) / GY;
        dim3 grid((m + 255) / 256, GY);
        kernelB<<<grid, 256>>>(P, Ps, n, m, rowChunk);
    }

    // reductions
    reduce_kernel<<<NB_RED, 256>>>(prob, n, m);
    final_kernel<<<1, 32>>>(out, NB_RED);
}

// round 2
// speedup vs baseline: 1.2857x; 1.2857x over previous
#include <cuda_runtime.h>
#include <cuda_bf16.h>
#include <math_constants.h>

#define N_MAX 30000
#define M_MAX 10000

// Scratch (no cudaMalloc allowed -> __device__ globals).
__device__ unsigned long long g_row_best[N_MAX];   // packed (sortkey(s)<<32)|argmin_j
__device__ unsigned int       g_col_best[M_MAX];   // sortkey(s)
#define NB_RED 120
__device__ float g_partials[NB_RED];

// ---------------------------------------------------------------------------
// Packed f32x2 helpers (Blackwell packed fp32 FMA: one instr = 2 lanes)
// ---------------------------------------------------------------------------
__device__ __forceinline__ unsigned long long pack2(float x, float y) {
    unsigned long long r;
    asm("mov.b64 %0, {%1, %2};" : "=l"(r) : "f"(x), "f"(y));
    return r;
}
__device__ __forceinline__ void unpack2(unsigned long long v, float& x, float& y) {
    asm("mov.b64 {%0, %1}, %2;" : "=f"(x), "=f"(y) : "l"(v));
}
__device__ __forceinline__ unsigned long long fma2(unsigned long long a,
                                                   unsigned long long b,
                                                   unsigned long long c) {
    unsigned long long d;
    asm("fma.rn.f32x2 %0, %1, %2, %3;" : "=l"(d) : "l"(a), "l"(b), "l"(c));
    return d;
}

// Sortable-uint encoding for signed floats (monotone: f0<f1 <=> key(f0)<key(f1))
__device__ __forceinline__ unsigned int fkey(float f) {
    unsigned int u = __float_as_uint(f);
    return (u & 0x80000000u) ? ~u : (u | 0x80000000u);
}
__device__ __forceinline__ float funkey(unsigned int k) {
    unsigned int u = (k & 0x80000000u) ? (k & 0x7FFFFFFFu) : ~k;
    return __uint_as_float(u);
}

// ---------------------------------------------------------------------------
// Init: poison min arrays to max key.
// ---------------------------------------------------------------------------
__global__ void init_kernel(int n, int m) {
    int i = blockIdx.x * blockDim.x + threadIdx.x;
    if (i < n) g_row_best[i] = 0xFFFFFFFFFFFFFFFFull;
    if (i < m) g_col_best[i] = 0xFFFFFFFFu;
}

// ---------------------------------------------------------------------------
// Tile layout: per column-pair k (2 points q0,q1 with c = 0.5*|q|^2):
//   tile[2k]   = (x0, x1, y0, y1)
//   tile[2k+1] = (z0, z1, c0, c1)
// Read in the hot loop as ulonglong2 -> {x01,y01} and {z01,c01} packed pairs.
// ---------------------------------------------------------------------------
#define PAIRS 512        // 1024 points per tile, 16 KB smem

// o->s: thread owns one P row, scans Ps tiles; tracks min s + argmin.
__global__ __launch_bounds__(256)
void kernelA(const float* __restrict__ P, const float* __restrict__ Ps,
             int n, int m, int colChunk) {
    __shared__ float4 tile[2 * PAIRS];

    const int row = blockIdx.x * blockDim.x + threadIdx.x;
    const int cbeg = blockIdx.y * colChunk;
    const int cend = min(cbeg + colChunk, m);

    float px = 0.f, py = 0.f, pz = 0.f;
    if (row < n) {
        px = P[row * 3 + 0];
        py = P[row * 3 + 1];
        pz = P[row * 3 + 2];
    }
    const unsigned long long npx2 = pack2(-px, -px);
    const unsigned long long npy2 = pack2(-py, -py);
    const unsigned long long npz2 = pack2(-pz, -pz);

    float best0 = CUDART_INF_F, best1 = CUDART_INF_F;
    int bidx0 = 0, bidx1 = 0;

    for (int t = cbeg; t < cend; t += 2 * PAIRS) {
        const int cnt = min(2 * PAIRS, cend - t);
        const int npair = (cnt + 1) >> 1;

        for (int k = threadIdx.x; k < npair; k += blockDim.x) {
            const int j0 = t + 2 * k;
            const int j1 = j0 + 1;
            const float* q0 = Ps + (size_t)j0 * 3;
            float x0 = q0[0], y0 = q0[1], z0 = q0[2];
            float c0 = 0.5f * fmaf(x0, x0, fmaf(y0, y0, z0 * z0));
            float x1 = 0.f, y1 = 0.f, z1 = 0.f, c1v = CUDART_INF_F;
            if (j1 < cend) {
                const float* q1 = Ps + (size_t)j1 * 3;
                x1 = q1[0]; y1 = q1[1]; z1 = q1[2];
                c1v = 0.5f * fmaf(x1, x1, fmaf(y1, y1, z1 * z1));
            }
            tile[2 * k + 0] = make_float4(x0, x1, y0, y1);
            tile[2 * k + 1] = make_float4(z0, z1, c0, c1v);
        }
        __syncthreads();

        if (row < n) {
            const ulonglong2* tl = (const ulonglong2*)tile;
            #pragma unroll 4
            for (int k = 0; k < npair; k++) {
                ulonglong2 t0 = tl[2 * k];       // {x01, y01}
                ulonglong2 t1 = tl[2 * k + 1];   // {z01, c01}
                unsigned long long s = fma2(npx2, t0.x, t1.y);
                s = fma2(npy2, t0.y, s);
                s = fma2(npz2, t1.x, s);
                float s0, s1;
                unpack2(s, s0, s1);
                const int j0 = t + 2 * k;
                if (s0 < best0) { best0 = s0; bidx0 = j0; }
                if (s1 < best1) { best1 = s1; bidx1 = j0 + 1; }
            }
        }
        __syncthreads();
    }

    if (row < n) {
        if (best1 < best0) { best0 = best1; bidx0 = bidx1; }
        unsigned long long pk =
            ((unsigned long long)fkey(best0) << 32) | (unsigned int)bidx0;
        atomicMin(&g_row_best[row], pk);
    }
}

// s->o: thread owns one Ps col, scans P tiles; tracks min s only.
__global__ __launch_bounds__(256)
void kernelB(const float* __restrict__ P, const float* __restrict__ Ps,
             int n, int m, int rowChunk) {
    __shared__ float4 tile[2 * PAIRS];

    const int col = blockIdx.x * blockDim.x + threadIdx.x;
    const int rbeg = blockIdx.y * rowChunk;
    const int rend = min(rbeg + rowChunk, n);

    float qx = 0.f, qy = 0.f, qz = 0.f;
    if (col < m) {
        qx = Ps[col * 3 + 0];
        qy = Ps[col * 3 + 1];
        qz = Ps[col * 3 + 2];
    }
    const unsigned long long nqx2 = pack2(-qx, -qx);
    const unsigned long long nqy2 = pack2(-qy, -qy);
    const unsigned long long nqz2 = pack2(-qz, -qz);

    float best0 = CUDART_INF_F, best1 = CUDART_INF_F;

    for (int t = rbeg; t < rend; t += 2 * PAIRS) {
        const int cnt = min(2 * PAIRS, rend - t);
        const int npair = (cnt + 1) >> 1;

        for (int k = threadIdx.x; k < npair; k += blockDim.x) {
            const int j0 = t + 2 * k;
            const int j1 = j0 + 1;
            const float* p0 = P + (size_t)j0 * 3;
            float x0 = p0[0], y0 = p0[1], z0 = p0[2];
            float c0 = 0.5f * fmaf(x0, x0, fmaf(y0, y0, z0 * z0));
            float x1 = 0.f, y1 = 0.f, z1 = 0.f, c1v = CUDART_INF_F;
            if (j1 < rend) {
                const float* p1 = P + (size_t)j1 * 3;
                x1 = p1[0]; y1 = p1[1]; z1 = p1[2];
                c1v = 0.5f * fmaf(x1, x1, fmaf(y1, y1, z1 * z1));
            }
            tile[2 * k + 0] = make_float4(x0, x1, y0, y1);
            tile[2 * k + 1] = make_float4(z0, z1, c0, c1v);
        }
        __syncthreads();

        if (col < m) {
            const ulonglong2* tl = (const ulonglong2*)tile;
            #pragma unroll 4
            for (int k = 0; k < npair; k++) {
                ulonglong2 t0 = tl[2 * k];
                ulonglong2 t1 = tl[2 * k + 1];
                unsigned long long s = fma2(nqx2, t0.x, t1.y);
                s = fma2(nqy2, t0.y, s);
                s = fma2(nqz2, t1.x, s);
                float s0, s1;
                unpack2(s, s0, s1);
                best0 = fminf(best0, s0);
                best1 = fminf(best1, s1);
            }
        }
        __syncthreads();
    }

    if (col < m) {
        float best = fminf(best0, best1);
        atomicMin(&g_col_best[col], fkey(best));
    }
}

// ---------------------------------------------------------------------------
// Reduction stage 1: per-block partial sums (fixed assignment -> deterministic).
// Recovers d2 = |point|^2 + 2*s_min from stored s-keys.
// ---------------------------------------------------------------------------
__global__ __launch_bounds__(256)
void reduce_kernel(const float* __restrict__ P, const float* __restrict__ Ps,
                   const float* __restrict__ prob, int n, int m) {
    __shared__ float ssum[256];
    const int stride = gridDim.x * blockDim.x;
    const int tid0 = blockIdx.x * blockDim.x + threadIdx.x;

    float sum = 0.0f;
    // o->s term: sqrt(d2) * prob[argmin]
    for (int i = tid0; i < n; i += stride) {
        unsigned long long pk = g_row_best[i];
        float s = funkey((unsigned int)(pk >> 32));
        int j = (int)(unsigned int)(pk & 0xFFFFFFFFu);
        float px = P[i * 3 + 0], py = P[i * 3 + 1], pz = P[i * 3 + 2];
        float p2 = fmaf(px, px, fmaf(py, py, pz * pz));
        float d2 = fmaf(2.0f, s, p2);
        sum += sqrtf(fmaxf(d2, 0.0f)) * prob[j];
    }
    // s->o term: sqrt(d2) * prob[j]
    for (int i = tid0; i < m; i += stride) {
        float s = funkey(g_col_best[i]);
        float qx = Ps[i * 3 + 0], qy = Ps[i * 3 + 1], qz = Ps[i * 3 + 2];
        float q2 = fmaf(qx, qx, fmaf(qy, qy, qz * qz));
        float d2 = fmaf(2.0f, s, q2);
        sum += sqrtf(fmaxf(d2, 0.0f)) * prob[i];
    }

    ssum[threadIdx.x] = sum;
    __syncthreads();
    for (int off = 128; off > 0; off >>= 1) {
        if (threadIdx.x < off) ssum[threadIdx.x] += ssum[threadIdx.x + off];
        __syncthreads();
    }
    if (threadIdx.x == 0) g_partials[blockIdx.x] = ssum[0];
}

__global__ void final_kernel(float* __restrict__ out, int nb) {
    if (threadIdx.x == 0 && blockIdx.x == 0) {
        float s = 0.0f;
        for (int i = 0; i < nb; i++) s += g_partials[i];
        out[0] = s;
    }
}

// ---------------------------------------------------------------------------
// Launch
// ---------------------------------------------------------------------------
extern "C" void kernel_launch(void* const* d_in, const int* in_sizes, int n_in,
                              void* d_out, int out_size) {
    const float* P    = (const float*)d_in[0];
    const float* Ps   = (const float*)d_in[1];
    const float* prob = (const float*)d_in[2];
    float* out = (float*)d_out;

    const int n = in_sizes[0] / 3;   // 30000
    const int m = in_sizes[1] / 3;   // 10000

    {
        int total = max(n, m);
        init_kernel<<<(total + 255) / 256, 256>>>(n, m);
    }

    // o->s: row blocks x column splits
    {
        const int GY = 5;
        const int colChunk = (m + GY - 1) / GY;
        dim3 grid((n + 255) / 256, GY);
        kernelA<<<grid, 256>>>(P, Ps, n, m, colChunk);
    }

    // s->o: Ps blocks x row splits
    {
        const int GY = 15;
        const int rowChunk = (n + GY - 1) / GY;
        dim3 grid((m + 255) / 256, GY);
        kernelB<<<grid, 256>>>(P, Ps, n, m, rowChunk);
    }

    reduce_kernel<<<NB_RED, 256>>>(P, Ps, prob, n, m);
    final_kernel<<<1, 32>>>(out, NB_RED);
}